// round 11
// baseline (speedup 1.0000x reference)
#include <cuda_runtime.h>
#include <cuda_fp16.h>
#include <cstdint>

#define EPSV 1e-5f

// ---------------- scratch (device globals; no allocation allowed) ----------------
__device__ __half g_p1h[8ull * 128 * 128 * 128];  // pooled stage 1 fp16: (B,C,128,128)
__device__ __half g_p2h[8ull * 128 * 64 * 64];    // pooled stage 2 fp16: (B,C,4096)
__device__ float  g_part[8ull * 16 * 128 * 128];  // gram partials: (B, 16 splits, C, C)
__device__ float  g_St[8ull * 128 * 128];         // sim transposed: [b][c][k]

// ---------------- kernel 1: dwconv s2 + BN + PReLU, fp32 in -> fp16 out (per batch) ----
__device__ __forceinline__ void load_row9(float* f, const float* rowp, int tx)
{
    float4 A = (tx > 0) ? *(const float4*)(rowp + tx * 8 - 4)
                        : make_float4(0.f, 0.f, 0.f, 0.f);
    float4 B = *(const float4*)(rowp + tx * 8);
    float4 C = *(const float4*)(rowp + tx * 8 + 4);
    f[0] = A.w;
    f[1] = B.x; f[2] = B.y; f[3] = B.z; f[4] = B.w;
    f[5] = C.x; f[6] = C.y; f[7] = C.z; f[8] = C.w;
}

__global__ void dwconv1_kernel(
    const float* __restrict__ in, __half* __restrict__ out,
    const float* __restrict__ w,
    const float* __restrict__ gamma, const float* __restrict__ beta,
    const float* __restrict__ mean, const float* __restrict__ var,
    const float* __restrict__ alpha)
{
    const int Win = 256, Wout = 128;
    int c  = blockIdx.z;               // channel 0..127
    int tx = threadIdx.x;              // 32 threads x 4 outputs
    int oy = blockIdx.x * blockDim.y + threadIdx.y;

    const float* ip = in + (size_t)c * 65536;

    float w0 = w[c*9+0], w1 = w[c*9+1], w2 = w[c*9+2];
    float w3 = w[c*9+3], w4 = w[c*9+4], w5 = w[c*9+5];
    float w6 = w[c*9+6], w7 = w[c*9+7], w8 = w[c*9+8];
    float inv  = gamma[c] * rsqrtf(var[c] + EPSV);
    float bias = beta[c] - mean[c] * inv;
    float a    = alpha[c];

    int iy = 2 * oy;
    float f0[9], f1[9], f2[9];
    if (oy > 0) load_row9(f0, ip + (size_t)(iy - 1) * Win, tx);
    else {
#pragma unroll
        for (int i = 0; i < 9; ++i) f0[i] = 0.f;
    }
    load_row9(f1, ip + (size_t)iy * Win, tx);
    load_row9(f2, ip + (size_t)(iy + 1) * Win, tx);

    float res[4];
#pragma unroll
    for (int j = 0; j < 4; ++j) {
        float s = w0 * f0[2*j] + w1 * f0[2*j+1] + w2 * f0[2*j+2]
                + w3 * f1[2*j] + w4 * f1[2*j+1] + w5 * f1[2*j+2]
                + w6 * f2[2*j] + w7 * f2[2*j+1] + w8 * f2[2*j+2];
        float y = s * inv + bias;
        res[j] = (y > 0.f) ? y : a * y;
    }
    __half2 h0 = __floats2half2_rn(res[0], res[1]);
    __half2 h1 = __floats2half2_rn(res[2], res[3]);
    __half* op = out + (size_t)c * 16384 + (size_t)oy * Wout + tx * 4;
    *(__half2*)op       = h0;
    *(__half2*)(op + 2) = h1;
}

// ---------------- kernel 2: dwconv s2 + BN + PReLU, fp16 in -> fp16 out (per batch) ----
__device__ __forceinline__ void load_row9h(float* f, const __half* rowp, int tx)
{
    if (tx > 0) {
        __half2 pv = *(const __half2*)(rowp + tx * 8 - 2);
        f[0] = __half2float(__high2half(pv));
    } else f[0] = 0.f;
    uint4 B = *(const uint4*)(rowp + tx * 8);
    const __half2* hb = (const __half2*)&B;
#pragma unroll
    for (int i = 0; i < 4; ++i) {
        float2 v = __half22float2(hb[i]);
        f[1 + 2*i] = v.x;
        f[2 + 2*i] = v.y;
    }
}

__global__ void dwconv2_kernel(
    const __half* __restrict__ in, __half* __restrict__ out,
    const float* __restrict__ w,
    const float* __restrict__ gamma, const float* __restrict__ beta,
    const float* __restrict__ mean, const float* __restrict__ var,
    const float* __restrict__ alpha)
{
    const int Win = 128, Wout = 64;
    int c  = blockIdx.z;
    int tx = threadIdx.x;              // 16 threads x 4 outputs
    int oy = blockIdx.x * blockDim.y + threadIdx.y;

    const __half* ip = in + (size_t)c * 16384;

    float w0 = w[c*9+0], w1 = w[c*9+1], w2 = w[c*9+2];
    float w3 = w[c*9+3], w4 = w[c*9+4], w5 = w[c*9+5];
    float w6 = w[c*9+6], w7 = w[c*9+7], w8 = w[c*9+8];
    float inv  = gamma[c] * rsqrtf(var[c] + EPSV);
    float bias = beta[c] - mean[c] * inv;
    float a    = alpha[c];

    int iy = 2 * oy;
    float f0[9], f1[9], f2[9];
    if (oy > 0) load_row9h(f0, ip + (size_t)(iy - 1) * Win, tx);
    else {
#pragma unroll
        for (int i = 0; i < 9; ++i) f0[i] = 0.f;
    }
    load_row9h(f1, ip + (size_t)iy * Win, tx);
    load_row9h(f2, ip + (size_t)(iy + 1) * Win, tx);

    float res[4];
#pragma unroll
    for (int j = 0; j < 4; ++j) {
        float s = w0 * f0[2*j] + w1 * f0[2*j+1] + w2 * f0[2*j+2]
                + w3 * f1[2*j] + w4 * f1[2*j+1] + w5 * f1[2*j+2]
                + w6 * f2[2*j] + w7 * f2[2*j+1] + w8 * f2[2*j+2];
        float y = s * inv + bias;
        res[j] = (y > 0.f) ? y : a * y;
    }
    __half2 h0 = __floats2half2_rn(res[0], res[1]);
    __half2 h1 = __floats2half2_rn(res[2], res[3]);
    __half* op = out + (size_t)c * 4096 + (size_t)oy * Wout + tx * 4;
    *(__half2*)op       = h0;
    *(__half2*)(op + 2) = h1;
}

// ---------------- common MMA helpers ----------------
__device__ __forceinline__ unsigned smem_u32(const void* p) {
    return (unsigned)__cvta_generic_to_shared(p);
}

#define LDSM_X4(r, addr) \
    asm volatile("ldmatrix.sync.aligned.m8n8.x4.shared.b16 {%0,%1,%2,%3},[%4];" \
        : "=r"((r)[0]), "=r"((r)[1]), "=r"((r)[2]), "=r"((r)[3]) : "r"(addr))

#define LDSM_X4_T(r, addr) \
    asm volatile("ldmatrix.sync.aligned.m8n8.x4.trans.shared.b16 {%0,%1,%2,%3},[%4];" \
        : "=r"((r)[0]), "=r"((r)[1]), "=r"((r)[2]), "=r"((r)[3]) : "r"(addr))

#define MMAF16(C, A, b0, b1) \
    asm volatile("mma.sync.aligned.m16n8k16.row.col.f32.f16.f16.f32 " \
        "{%0,%1,%2,%3},{%4,%5,%6,%7},{%8,%9},{%0,%1,%2,%3};" \
        : "+f"((C)[0]), "+f"((C)[1]), "+f"((C)[2]), "+f"((C)[3]) \
        : "r"((A)[0]), "r"((A)[1]), "r"((A)[2]), "r"((A)[3]), "r"(b0), "r"(b1))

#define CP_ASYNC16(dst, src) \
    asm volatile("cp.async.cg.shared.global [%0],[%1],16;" :: "r"(dst), "l"(src))
#define CP_COMMIT() asm volatile("cp.async.commit_group;")
#define CP_WAIT0()  asm volatile("cp.async.wait_group 0;" ::: "memory")

// ---------------- kernel 3: gram partials via fp16 MMA (per batch) ----------------
#define LDP 264

__global__ __launch_bounds__(256) void gram_mma_kernel(int b)
{
    extern __shared__ __half P[];       // [128 c][LDP]
    int s = blockIdx.x;
    int tid = threadIdx.x, warp = tid >> 5, lane = tid & 31;

    const __half* src = g_p2h + (size_t)b * 524288 + s * 256;
#pragma unroll
    for (int i = 0; i < 16; ++i) {
        int idx = i * 256 + tid;
        int c = idx >> 5, j = idx & 31;
        *(uint4*)(P + c * LDP + j * 8) = *(const uint4*)(src + (size_t)c * 4096 + j * 8);
    }
    __syncthreads();

    int i0 = (warp >> 1) * 32;
    int j0 = (warp & 1) * 64;
    int r  = lane & 15, q = lane >> 4;
    int br = (lane & 7) | ((lane >> 4) << 3);
    int bq = (lane >> 3) & 1;

    float acc[2][8][4];
#pragma unroll
    for (int mf = 0; mf < 2; ++mf)
#pragma unroll
        for (int nf = 0; nf < 8; ++nf)
#pragma unroll
            for (int e = 0; e < 4; ++e) acc[mf][nf][e] = 0.f;

#pragma unroll
    for (int ks = 0; ks < 16; ++ks) {
        int k0 = ks * 16;
        unsigned ah[2][4];
#pragma unroll
        for (int mf = 0; mf < 2; ++mf)
            LDSM_X4(ah[mf], smem_u32(P + (i0 + mf * 16 + r) * LDP + k0 + q * 8));
#pragma unroll
        for (int nc = 0; nc < 4; ++nc) {
            unsigned bf[4];
            LDSM_X4(bf, smem_u32(P + (j0 + nc * 16 + br) * LDP + k0 + bq * 8));
#pragma unroll
            for (int mf = 0; mf < 2; ++mf) {
                MMAF16(acc[mf][nc * 2],     ah[mf], bf[0], bf[1]);
                MMAF16(acc[mf][nc * 2 + 1], ah[mf], bf[2], bf[3]);
            }
        }
    }

    float* dst = g_part + ((size_t)b * 16 + s) * 16384;
    int rbase = i0 + (lane >> 2);
    int cbase = j0 + ((lane & 3) << 1);
#pragma unroll
    for (int mf = 0; mf < 2; ++mf) {
#pragma unroll
        for (int nf = 0; nf < 8; ++nf) {
            float* p0 = dst + (size_t)(rbase + mf * 16) * 128 + cbase + nf * 8;
            float* p1 = p0 + 8 * 128;
            *(float2*)p0 = make_float2(acc[mf][nf][0], acc[mf][nf][1]);
            *(float2*)p1 = make_float2(acc[mf][nf][2], acc[mf][nf][3]);
        }
    }
}

// ---------------- kernel 4: reduce 16 partials, scale, softmax (per batch) ----------
__global__ void softmax_kernel(int b)
{
    int i = blockIdx.x, j = threadIdx.x;   // i = row k, j = col c
    const float* p = g_part + (size_t)b * 16 * 16384 + (size_t)i * 128 + j;
    float g = 0.f;
#pragma unroll
    for (int s = 0; s < 16; ++s) g += p[(size_t)s * 16384];
    g *= (1.0f / 64.0f);   // (64*64)^-0.5

    __shared__ float buf[128];
    buf[j] = g;
    __syncthreads();
    for (int off = 64; off > 0; off >>= 1) {
        if (j < off) buf[j] = fmaxf(buf[j], buf[j + off]);
        __syncthreads();
    }
    float m = buf[0];
    __syncthreads();
    float e = __expf(g - m);
    buf[j] = e;
    __syncthreads();
    for (int off = 64; off > 0; off >>= 1) {
        if (j < off) buf[j] = buf[j] + buf[j + off];
        __syncthreads();
    }
    float r = e / buf[0];
    g_St[(size_t)b * 16384 + (size_t)j * 128 + i] = r;   // [b][c][k]
}

// ---------------- kernel 5: attention einsum, fp16 MMA (per batch) ----------------
#define LDA 136
#define LDB 72
#define TN  64
#define NSUB 8

#define ATTN_SMEM 104448

__global__ __launch_bounds__(256, 2) void attn_mma_kernel(const float* __restrict__ x,
                                                          float* __restrict__ out,
                                                          int b)
{
    extern __shared__ char smraw[];
    __half* Ahi = (__half*)smraw;              // [128 c][LDA k]
    __half* B0  = Ahi + 128 * LDA;             // [128 k][LDB n], double buffered
    __half* B1  = B0 + 128 * LDB;
    float*  Xs  = (float*)(B1 + 128 * LDB);    // staging [128 k][64 n] fp32

    int tid  = threadIdx.x;
    int warp = tid >> 5, lane = tid & 31;

    const float* xb = x + (size_t)b * 128 * 65536;
    float*       ob = out + (size_t)b * 128 * 65536;

    {
        int n0 = blockIdx.x * (NSUB * TN);
#pragma unroll
        for (int i = 0; i < 8; ++i) {
            int idx = i * 256 + tid;
            int k = idx >> 4, c4 = idx & 15;
            CP_ASYNC16(smem_u32(Xs + k * TN + c4 * 4),
                       xb + (size_t)k * 65536 + n0 + c4 * 4);
        }
        CP_COMMIT();
    }

    {
        const float* Sp = g_St + (size_t)b * 16384;
#pragma unroll
        for (int i = 0; i < 16; ++i) {
            int idx = i * 256 + tid;
            int c = idx >> 5, k4 = (idx & 31) * 4;
            float4 v = *(const float4*)(Sp + c * 128 + k4);
            __half* ph = Ahi + c * LDA + k4;
            *(__half2*)(ph)     = __floats2half2_rn(v.x, v.y);
            *(__half2*)(ph + 2) = __floats2half2_rn(v.z, v.w);
        }
    }

    int mw = (warp >> 1) * 32;
    int nw = (warp & 1) * 32;
    int r  = lane & 15, q = lane >> 4;

    for (int t = 0; t < NSUB; ++t) {
        __half* Bp = (t & 1) ? B1 : B0;
        int n0 = (blockIdx.x * NSUB + t) * TN;

        CP_WAIT0();
#pragma unroll
        for (int i = 0; i < 8; ++i) {
            int idx = i * 256 + tid;
            int k = idx >> 4, c4 = idx & 15;
            float4 v = *(const float4*)(Xs + k * TN + c4 * 4);
            __half* ph = Bp + k * LDB + c4 * 4;
            *(__half2*)(ph)     = __floats2half2_rn(v.x, v.y);
            *(__half2*)(ph + 2) = __floats2half2_rn(v.z, v.w);
        }

        if (t + 1 < NSUB) {
            int n0n = n0 + TN;
#pragma unroll
            for (int i = 0; i < 8; ++i) {
                int idx = i * 256 + tid;
                int k = idx >> 4, c4 = idx & 15;
                CP_ASYNC16(smem_u32(Xs + k * TN + c4 * 4),
                           xb + (size_t)k * 65536 + n0n + c4 * 4);
            }
            CP_COMMIT();
        }

        __syncthreads();

        float acc[2][4][4];
#pragma unroll
        for (int mf = 0; mf < 2; ++mf)
#pragma unroll
            for (int nf = 0; nf < 4; ++nf)
#pragma unroll
                for (int e = 0; e < 4; ++e) acc[mf][nf][e] = 0.f;

#pragma unroll
        for (int ks = 0; ks < 8; ++ks) {
            int k0 = ks * 16;
            unsigned ah[2][4];
#pragma unroll
            for (int mf = 0; mf < 2; ++mf)
                LDSM_X4(ah[mf], smem_u32(Ahi + (mw + mf * 16 + r) * LDA + k0 + q * 8));
#pragma unroll
            for (int nc = 0; nc < 2; ++nc) {
                unsigned bf[4];
                LDSM_X4_T(bf, smem_u32(Bp + (k0 + r) * LDB + nw + nc * 16 + q * 8));
#pragma unroll
                for (int mf = 0; mf < 2; ++mf) {
#pragma unroll
                    for (int h = 0; h < 2; ++h) {
                        float* C = acc[mf][nc * 2 + h];
                        MMAF16(C, ah[mf], bf[2 * h], bf[2 * h + 1]);
                    }
                }
            }
        }

        int rbase = mw + (lane >> 2);
        int cbase = nw + ((lane & 3) << 1);
#pragma unroll
        for (int mf = 0; mf < 2; ++mf) {
#pragma unroll
            for (int nf = 0; nf < 4; ++nf) {
                float* p0 = ob + (size_t)(rbase + mf * 16) * 65536 + n0 + cbase + nf * 8;
                float* p1 = p0 + 8ull * 65536;
                *(float2*)p0 = make_float2(acc[mf][nf][0], acc[mf][nf][1]);
                *(float2*)p1 = make_float2(acc[mf][nf][2], acc[mf][nf][3]);
            }
        }
    }
}

// ---------------- launch: per-batch pipelined fork/join ----------------
extern "C" void kernel_launch(void* const* d_in, const int* in_sizes, int n_in,
                              void* d_out, int out_size)
{
    (void)in_sizes; (void)n_in; (void)out_size;
    const float* x    = (const float*)d_in[0];
    const float* c1w  = (const float*)d_in[1];
    const float* g1   = (const float*)d_in[2];
    const float* b1   = (const float*)d_in[3];
    const float* m1   = (const float*)d_in[4];
    const float* v1   = (const float*)d_in[5];
    const float* a1   = (const float*)d_in[6];
    const float* c2w  = (const float*)d_in[7];
    const float* g2   = (const float*)d_in[8];
    const float* b2   = (const float*)d_in[9];
    const float* m2   = (const float*)d_in[10];
    const float* v2   = (const float*)d_in[11];
    const float* a2   = (const float*)d_in[12];
    float* out = (float*)d_out;

    void* tmp;
    cudaGetSymbolAddress(&tmp, g_p1h);  __half* p1 = (__half*)tmp;
    cudaGetSymbolAddress(&tmp, g_p2h);  __half* p2 = (__half*)tmp;

    // one-time host-side objects (no device memory)
    static cudaStream_t sPrep = nullptr;
    static cudaEvent_t  evFork = nullptr;
    static cudaEvent_t  evPrep[8];
    if (!sPrep) {
        cudaStreamCreateWithFlags(&sPrep, cudaStreamNonBlocking);
        cudaEventCreateWithFlags(&evFork, cudaEventDisableTiming);
        for (int b = 0; b < 8; ++b)
            cudaEventCreateWithFlags(&evPrep[b], cudaEventDisableTiming);
        cudaFuncSetAttribute(gram_mma_kernel,
                             cudaFuncAttributeMaxDynamicSharedMemorySize, 128 * LDP * 2);
        cudaFuncSetAttribute(attn_mma_kernel,
                             cudaFuncAttributeMaxDynamicSharedMemorySize, ATTN_SMEM);
    }

    cudaStream_t s0 = 0;   // capture stream (default)

    // fork: prep stream joins the capture graph
    cudaEventRecord(evFork, s0);
    cudaStreamWaitEvent(sPrep, evFork, 0);

    for (int b = 0; b < 8; ++b) {
        const float* xb = x + (size_t)b * 8388608;
        __half* p1b = p1 + (size_t)b * 2097152;
        __half* p2b = p2 + (size_t)b * 524288;
        dwconv1_kernel<<<dim3(16, 1, 128), dim3(32, 8), 0, sPrep>>>(
            xb, p1b, c1w, g1, b1, m1, v1, a1);
        dwconv2_kernel<<<dim3(4, 1, 128), dim3(16, 16), 0, sPrep>>>(
            p1b, p2b, c2w, g2, b2, m2, v2, a2);
        gram_mma_kernel<<<16, 256, 128 * LDP * 2, sPrep>>>(b);
        softmax_kernel<<<128, 128, 0, sPrep>>>(b);
        cudaEventRecord(evPrep[b], sPrep);
    }

    // join: attn[b] on the capture stream, gated on prep[b]
    for (int b = 0; b < 8; ++b) {
        cudaStreamWaitEvent(s0, evPrep[b], 0);
        attn_mma_kernel<<<128, 256, ATTN_SMEM, s0>>>(x, out, b);
    }
}

// round 12
// speedup vs baseline: 1.2543x; 1.2543x over previous
#include <cuda_runtime.h>
#include <cuda_fp16.h>
#include <cstdint>

#define EPSV 1e-5f

// ---------------- scratch (device globals; no allocation allowed) ----------------
__device__ __half g_p1h[8ull * 128 * 128 * 128];  // pooled stage 1 fp16: (B,C,128,128)
__device__ __half g_p2h[8ull * 128 * 64 * 64];    // pooled stage 2 fp16: (B,C,4096)
__device__ float  g_part[8ull * 16 * 128 * 128];  // gram partials: (B, 16 splits, C, C)
__device__ float  g_St[8ull * 128 * 128];         // sim transposed: [b][c][k]

// ---------------- kernel 1: dwconv s2 + BN + PReLU, fp32 in -> fp16 out ----------------
__device__ __forceinline__ void load_row9(float* f, const float* rowp, int tx)
{
    float4 A = (tx > 0) ? *(const float4*)(rowp + tx * 8 - 4)
                        : make_float4(0.f, 0.f, 0.f, 0.f);
    float4 B = *(const float4*)(rowp + tx * 8);
    float4 C = *(const float4*)(rowp + tx * 8 + 4);
    f[0] = A.w;
    f[1] = B.x; f[2] = B.y; f[3] = B.z; f[4] = B.w;
    f[5] = C.x; f[6] = C.y; f[7] = C.z; f[8] = C.w;
}

__global__ void dwconv1_kernel(
    const float* __restrict__ in, __half* __restrict__ out,
    const float* __restrict__ w,
    const float* __restrict__ gamma, const float* __restrict__ beta,
    const float* __restrict__ mean, const float* __restrict__ var,
    const float* __restrict__ alpha, int bc0)
{
    const int Win = 256, Wout = 128;
    int bc = bc0 + blockIdx.z;         // b*128 + c
    int c  = bc & 127;
    int tx = threadIdx.x;              // 32 threads x 4 outputs
    int oy = blockIdx.x * blockDim.y + threadIdx.y;

    const float* ip = in + (size_t)bc * 65536;

    float w0 = w[c*9+0], w1 = w[c*9+1], w2 = w[c*9+2];
    float w3 = w[c*9+3], w4 = w[c*9+4], w5 = w[c*9+5];
    float w6 = w[c*9+6], w7 = w[c*9+7], w8 = w[c*9+8];
    float inv  = gamma[c] * rsqrtf(var[c] + EPSV);
    float bias = beta[c] - mean[c] * inv;
    float a    = alpha[c];

    int iy = 2 * oy;
    float f0[9], f1[9], f2[9];
    if (oy > 0) load_row9(f0, ip + (size_t)(iy - 1) * Win, tx);
    else {
#pragma unroll
        for (int i = 0; i < 9; ++i) f0[i] = 0.f;
    }
    load_row9(f1, ip + (size_t)iy * Win, tx);
    load_row9(f2, ip + (size_t)(iy + 1) * Win, tx);

    float res[4];
#pragma unroll
    for (int j = 0; j < 4; ++j) {
        float s = w0 * f0[2*j] + w1 * f0[2*j+1] + w2 * f0[2*j+2]
                + w3 * f1[2*j] + w4 * f1[2*j+1] + w5 * f1[2*j+2]
                + w6 * f2[2*j] + w7 * f2[2*j+1] + w8 * f2[2*j+2];
        float y = s * inv + bias;
        res[j] = (y > 0.f) ? y : a * y;
    }
    __half2 h0 = __floats2half2_rn(res[0], res[1]);
    __half2 h1 = __floats2half2_rn(res[2], res[3]);
    __half* op = out + (size_t)bc * 16384 + (size_t)oy * Wout + tx * 4;
    *(__half2*)op       = h0;
    *(__half2*)(op + 2) = h1;
}

// ---------------- kernel 2: dwconv s2 + BN + PReLU, fp16 in -> fp16 out ----------------
__device__ __forceinline__ void load_row9h(float* f, const __half* rowp, int tx)
{
    if (tx > 0) {
        __half2 pv = *(const __half2*)(rowp + tx * 8 - 2);
        f[0] = __half2float(__high2half(pv));
    } else f[0] = 0.f;
    uint4 B = *(const uint4*)(rowp + tx * 8);
    const __half2* hb = (const __half2*)&B;
#pragma unroll
    for (int i = 0; i < 4; ++i) {
        float2 v = __half22float2(hb[i]);
        f[1 + 2*i] = v.x;
        f[2 + 2*i] = v.y;
    }
}

__global__ void dwconv2_kernel(
    const __half* __restrict__ in, __half* __restrict__ out,
    const float* __restrict__ w,
    const float* __restrict__ gamma, const float* __restrict__ beta,
    const float* __restrict__ mean, const float* __restrict__ var,
    const float* __restrict__ alpha, int bc0)
{
    const int Win = 128, Wout = 64;
    int bc = bc0 + blockIdx.z;
    int c  = bc & 127;
    int tx = threadIdx.x;              // 16 threads x 4 outputs
    int oy = blockIdx.x * blockDim.y + threadIdx.y;

    const __half* ip = in + (size_t)bc * 16384;

    float w0 = w[c*9+0], w1 = w[c*9+1], w2 = w[c*9+2];
    float w3 = w[c*9+3], w4 = w[c*9+4], w5 = w[c*9+5];
    float w6 = w[c*9+6], w7 = w[c*9+7], w8 = w[c*9+8];
    float inv  = gamma[c] * rsqrtf(var[c] + EPSV);
    float bias = beta[c] - mean[c] * inv;
    float a    = alpha[c];

    int iy = 2 * oy;
    float f0[9], f1[9], f2[9];
    if (oy > 0) load_row9h(f0, ip + (size_t)(iy - 1) * Win, tx);
    else {
#pragma unroll
        for (int i = 0; i < 9; ++i) f0[i] = 0.f;
    }
    load_row9h(f1, ip + (size_t)iy * Win, tx);
    load_row9h(f2, ip + (size_t)(iy + 1) * Win, tx);

    float res[4];
#pragma unroll
    for (int j = 0; j < 4; ++j) {
        float s = w0 * f0[2*j] + w1 * f0[2*j+1] + w2 * f0[2*j+2]
                + w3 * f1[2*j] + w4 * f1[2*j+1] + w5 * f1[2*j+2]
                + w6 * f2[2*j] + w7 * f2[2*j+1] + w8 * f2[2*j+2];
        float y = s * inv + bias;
        res[j] = (y > 0.f) ? y : a * y;
    }
    __half2 h0 = __floats2half2_rn(res[0], res[1]);
    __half2 h1 = __floats2half2_rn(res[2], res[3]);
    __half* op = out + (size_t)bc * 4096 + (size_t)oy * Wout + tx * 4;
    *(__half2*)op       = h0;
    *(__half2*)(op + 2) = h1;
}

// ---------------- common MMA helpers ----------------
__device__ __forceinline__ unsigned smem_u32(const void* p) {
    return (unsigned)__cvta_generic_to_shared(p);
}

#define LDSM_X4(r, addr) \
    asm volatile("ldmatrix.sync.aligned.m8n8.x4.shared.b16 {%0,%1,%2,%3},[%4];" \
        : "=r"((r)[0]), "=r"((r)[1]), "=r"((r)[2]), "=r"((r)[3]) : "r"(addr))

#define LDSM_X4_T(r, addr) \
    asm volatile("ldmatrix.sync.aligned.m8n8.x4.trans.shared.b16 {%0,%1,%2,%3},[%4];" \
        : "=r"((r)[0]), "=r"((r)[1]), "=r"((r)[2]), "=r"((r)[3]) : "r"(addr))

#define MMAF16(C, A, b0, b1) \
    asm volatile("mma.sync.aligned.m16n8k16.row.col.f32.f16.f16.f32 " \
        "{%0,%1,%2,%3},{%4,%5,%6,%7},{%8,%9},{%0,%1,%2,%3};" \
        : "+f"((C)[0]), "+f"((C)[1]), "+f"((C)[2]), "+f"((C)[3]) \
        : "r"((A)[0]), "r"((A)[1]), "r"((A)[2]), "r"((A)[3]), "r"(b0), "r"(b1))

#define CP_ASYNC16(dst, src) \
    asm volatile("cp.async.cg.shared.global [%0],[%1],16;" :: "r"(dst), "l"(src))
#define CP_COMMIT() asm volatile("cp.async.commit_group;")
#define CP_WAIT0()  asm volatile("cp.async.wait_group 0;" ::: "memory")

// ---------------- kernel 3: gram partials via fp16 MMA ----------------
#define LDP 264

__global__ __launch_bounds__(256) void gram_mma_kernel(int b0)
{
    extern __shared__ __half P[];       // [128 c][LDP]
    int s = blockIdx.x, b = b0 + blockIdx.y;
    int tid = threadIdx.x, warp = tid >> 5, lane = tid & 31;

    const __half* src = g_p2h + (size_t)b * 524288 + s * 256;
#pragma unroll
    for (int i = 0; i < 16; ++i) {
        int idx = i * 256 + tid;
        int c = idx >> 5, j = idx & 31;
        *(uint4*)(P + c * LDP + j * 8) = *(const uint4*)(src + (size_t)c * 4096 + j * 8);
    }
    __syncthreads();

    int i0 = (warp >> 1) * 32;
    int j0 = (warp & 1) * 64;
    int r  = lane & 15, q = lane >> 4;
    int br = (lane & 7) | ((lane >> 4) << 3);
    int bq = (lane >> 3) & 1;

    float acc[2][8][4];
#pragma unroll
    for (int mf = 0; mf < 2; ++mf)
#pragma unroll
        for (int nf = 0; nf < 8; ++nf)
#pragma unroll
            for (int e = 0; e < 4; ++e) acc[mf][nf][e] = 0.f;

#pragma unroll
    for (int ks = 0; ks < 16; ++ks) {
        int k0 = ks * 16;
        unsigned ah[2][4];
#pragma unroll
        for (int mf = 0; mf < 2; ++mf)
            LDSM_X4(ah[mf], smem_u32(P + (i0 + mf * 16 + r) * LDP + k0 + q * 8));
#pragma unroll
        for (int nc = 0; nc < 4; ++nc) {
            unsigned bf[4];
            LDSM_X4(bf, smem_u32(P + (j0 + nc * 16 + br) * LDP + k0 + bq * 8));
#pragma unroll
            for (int mf = 0; mf < 2; ++mf) {
                MMAF16(acc[mf][nc * 2],     ah[mf], bf[0], bf[1]);
                MMAF16(acc[mf][nc * 2 + 1], ah[mf], bf[2], bf[3]);
            }
        }
    }

    float* dst = g_part + ((size_t)b * 16 + s) * 16384;
    int rbase = i0 + (lane >> 2);
    int cbase = j0 + ((lane & 3) << 1);
#pragma unroll
    for (int mf = 0; mf < 2; ++mf) {
#pragma unroll
        for (int nf = 0; nf < 8; ++nf) {
            float* p0 = dst + (size_t)(rbase + mf * 16) * 128 + cbase + nf * 8;
            float* p1 = p0 + 8 * 128;
            *(float2*)p0 = make_float2(acc[mf][nf][0], acc[mf][nf][1]);
            *(float2*)p1 = make_float2(acc[mf][nf][2], acc[mf][nf][3]);
        }
    }
}

// ---------------- kernel 4: reduce 16 partials, scale, softmax; TRANSPOSED store ----
__global__ void softmax_kernel(int b0)
{
    int i = blockIdx.x, b = b0 + blockIdx.y, j = threadIdx.x;
    const float* p = g_part + (size_t)b * 16 * 16384 + (size_t)i * 128 + j;
    float g = 0.f;
#pragma unroll
    for (int s = 0; s < 16; ++s) g += p[(size_t)s * 16384];
    g *= (1.0f / 64.0f);   // (64*64)^-0.5

    __shared__ float buf[128];
    buf[j] = g;
    __syncthreads();
    for (int off = 64; off > 0; off >>= 1) {
        if (j < off) buf[j] = fmaxf(buf[j], buf[j + off]);
        __syncthreads();
    }
    float m = buf[0];
    __syncthreads();
    float e = __expf(g - m);
    buf[j] = e;
    __syncthreads();
    for (int off = 64; off > 0; off >>= 1) {
        if (j < off) buf[j] = buf[j] + buf[j + off];
        __syncthreads();
    }
    float r = e / buf[0];
    g_St[(size_t)b * 16384 + (size_t)j * 128 + i] = r;   // [b][c][k]
}

// ---------------- kernel 5: attention einsum, fp16 MMA ----------------
#define LDA 136
#define LDB 72
#define TN  64
#define NSUB 8

#define ATTN_SMEM 104448

__global__ __launch_bounds__(256, 2) void attn_mma_kernel(const float* __restrict__ x,
                                                          float* __restrict__ out,
                                                          int b0)
{
    extern __shared__ char smraw[];
    __half* Ahi = (__half*)smraw;              // [128 c][LDA k]
    __half* B0  = Ahi + 128 * LDA;             // [128 k][LDB n], double buffered
    __half* B1  = B0 + 128 * LDB;
    float*  Xs  = (float*)(B1 + 128 * LDB);    // staging [128 k][64 n] fp32

    int b    = b0 + blockIdx.y;
    int tid  = threadIdx.x;
    int warp = tid >> 5, lane = tid & 31;

    const float* xb = x + (size_t)b * 128 * 65536;
    float*       ob = out + (size_t)b * 128 * 65536;

    {
        int n0 = blockIdx.x * (NSUB * TN);
#pragma unroll
        for (int i = 0; i < 8; ++i) {
            int idx = i * 256 + tid;
            int k = idx >> 4, c4 = idx & 15;
            CP_ASYNC16(smem_u32(Xs + k * TN + c4 * 4),
                       xb + (size_t)k * 65536 + n0 + c4 * 4);
        }
        CP_COMMIT();
    }

    {
        const float* Sp = g_St + (size_t)b * 16384;
#pragma unroll
        for (int i = 0; i < 16; ++i) {
            int idx = i * 256 + tid;
            int c = idx >> 5, k4 = (idx & 31) * 4;
            float4 v = *(const float4*)(Sp + c * 128 + k4);
            __half* ph = Ahi + c * LDA + k4;
            *(__half2*)(ph)     = __floats2half2_rn(v.x, v.y);
            *(__half2*)(ph + 2) = __floats2half2_rn(v.z, v.w);
        }
    }

    int mw = (warp >> 1) * 32;
    int nw = (warp & 1) * 32;
    int r  = lane & 15, q = lane >> 4;

    for (int t = 0; t < NSUB; ++t) {
        __half* Bp = (t & 1) ? B1 : B0;
        int n0 = (blockIdx.x * NSUB + t) * TN;

        CP_WAIT0();
#pragma unroll
        for (int i = 0; i < 8; ++i) {
            int idx = i * 256 + tid;
            int k = idx >> 4, c4 = idx & 15;
            float4 v = *(const float4*)(Xs + k * TN + c4 * 4);
            __half* ph = Bp + k * LDB + c4 * 4;
            *(__half2*)(ph)     = __floats2half2_rn(v.x, v.y);
            *(__half2*)(ph + 2) = __floats2half2_rn(v.z, v.w);
        }

        if (t + 1 < NSUB) {
            int n0n = n0 + TN;
#pragma unroll
            for (int i = 0; i < 8; ++i) {
                int idx = i * 256 + tid;
                int k = idx >> 4, c4 = idx & 15;
                CP_ASYNC16(smem_u32(Xs + k * TN + c4 * 4),
                           xb + (size_t)k * 65536 + n0n + c4 * 4);
            }
            CP_COMMIT();
        }

        __syncthreads();

        float acc[2][4][4];
#pragma unroll
        for (int mf = 0; mf < 2; ++mf)
#pragma unroll
            for (int nf = 0; nf < 4; ++nf)
#pragma unroll
                for (int e = 0; e < 4; ++e) acc[mf][nf][e] = 0.f;

#pragma unroll
        for (int ks = 0; ks < 8; ++ks) {
            int k0 = ks * 16;
            unsigned ah[2][4];
#pragma unroll
            for (int mf = 0; mf < 2; ++mf)
                LDSM_X4(ah[mf], smem_u32(Ahi + (mw + mf * 16 + r) * LDA + k0 + q * 8));
#pragma unroll
            for (int nc = 0; nc < 2; ++nc) {
                unsigned bf[4];
                LDSM_X4_T(bf, smem_u32(Bp + (k0 + r) * LDB + nw + nc * 16 + q * 8));
#pragma unroll
                for (int mf = 0; mf < 2; ++mf) {
#pragma unroll
                    for (int h = 0; h < 2; ++h) {
                        float* C = acc[mf][nc * 2 + h];
                        MMAF16(C, ah[mf], bf[2 * h], bf[2 * h + 1]);
                    }
                }
            }
        }

        int rbase = mw + (lane >> 2);
        int cbase = nw + ((lane & 3) << 1);
#pragma unroll
        for (int mf = 0; mf < 2; ++mf) {
#pragma unroll
            for (int nf = 0; nf < 4; ++nf) {
                float* p0 = ob + (size_t)(rbase + mf * 16) * 65536 + n0 + cbase + nf * 8;
                float* p1 = p0 + 8ull * 65536;
                *(float2*)p0 = make_float2(acc[mf][nf][0], acc[mf][nf][1]);
                *(float2*)p1 = make_float2(acc[mf][nf][2], acc[mf][nf][3]);
            }
        }
    }
}

// ---------------- launch: two-stream, half-batch pipeline ----------------
extern "C" void kernel_launch(void* const* d_in, const int* in_sizes, int n_in,
                              void* d_out, int out_size)
{
    (void)in_sizes; (void)n_in; (void)out_size;
    const float* x    = (const float*)d_in[0];
    const float* c1w  = (const float*)d_in[1];
    const float* g1   = (const float*)d_in[2];
    const float* b1   = (const float*)d_in[3];
    const float* m1   = (const float*)d_in[4];
    const float* v1   = (const float*)d_in[5];
    const float* a1   = (const float*)d_in[6];
    const float* c2w  = (const float*)d_in[7];
    const float* g2   = (const float*)d_in[8];
    const float* b2   = (const float*)d_in[9];
    const float* m2   = (const float*)d_in[10];
    const float* v2   = (const float*)d_in[11];
    const float* a2   = (const float*)d_in[12];
    float* out = (float*)d_out;

    void* tmp;
    cudaGetSymbolAddress(&tmp, g_p1h);  __half* p1 = (__half*)tmp;
    cudaGetSymbolAddress(&tmp, g_p2h);  __half* p2 = (__half*)tmp;

    static cudaStream_t sPrep = nullptr;
    static cudaEvent_t  evFork = nullptr, evA = nullptr, evB = nullptr;
    if (!sPrep) {
        cudaStreamCreateWithFlags(&sPrep, cudaStreamNonBlocking);
        cudaEventCreateWithFlags(&evFork, cudaEventDisableTiming);
        cudaEventCreateWithFlags(&evA, cudaEventDisableTiming);
        cudaEventCreateWithFlags(&evB, cudaEventDisableTiming);
        cudaFuncSetAttribute(gram_mma_kernel,
                             cudaFuncAttributeMaxDynamicSharedMemorySize, 128 * LDP * 2);
        cudaFuncSetAttribute(attn_mma_kernel,
                             cudaFuncAttributeMaxDynamicSharedMemorySize, ATTN_SMEM);
    }

    cudaStream_t s0 = 0;

    cudaEventRecord(evFork, s0);
    cudaStreamWaitEvent(sPrep, evFork, 0);

    // ---- prep half A (batches 0-3)
    dwconv1_kernel<<<dim3(16, 1, 512), dim3(32, 8), 0, sPrep>>>(
        x, p1, c1w, g1, b1, m1, v1, a1, 0);
    dwconv2_kernel<<<dim3(4, 1, 512), dim3(16, 16), 0, sPrep>>>(
        p1, p2, c2w, g2, b2, m2, v2, a2, 0);
    gram_mma_kernel<<<dim3(16, 4), 256, 128 * LDP * 2, sPrep>>>(0);
    softmax_kernel<<<dim3(128, 4), 128, 0, sPrep>>>(0);
    cudaEventRecord(evA, sPrep);

    // ---- prep half B (batches 4-7)
    dwconv1_kernel<<<dim3(16, 1, 512), dim3(32, 8), 0, sPrep>>>(
        x, p1, c1w, g1, b1, m1, v1, a1, 512);
    dwconv2_kernel<<<dim3(4, 1, 512), dim3(16, 16), 0, sPrep>>>(
        p1, p2, c2w, g2, b2, m2, v2, a2, 512);
    gram_mma_kernel<<<dim3(16, 4), 256, 128 * LDP * 2, sPrep>>>(4);
    softmax_kernel<<<dim3(128, 4), 128, 0, sPrep>>>(4);
    cudaEventRecord(evB, sPrep);

    // ---- attn halves on the capture stream (attnA overlaps prepB)
    cudaStreamWaitEvent(s0, evA, 0);
    attn_mma_kernel<<<dim3(128, 4), 256, ATTN_SMEM, s0>>>(x, out, 0);
    cudaStreamWaitEvent(s0, evB, 0);
    attn_mma_kernel<<<dim3(128, 4), 256, ATTN_SMEM, s0>>>(x, out, 4);
}

// round 13
// speedup vs baseline: 1.3034x; 1.0391x over previous
#include <cuda_runtime.h>
#include <cuda_fp16.h>
#include <cstdint>

#define EPSV 1e-5f

// ---------------- scratch (device globals; no allocation allowed) ----------------
__device__ __half g_x16[8ull * 128 * 256 * 256];  // x in fp16: (B,C,256,256)
__device__ __half g_p1h[8ull * 128 * 128 * 128];  // pooled stage 1 fp16
__device__ __half g_p2h[8ull * 128 * 64 * 64];    // pooled stage 2 fp16
__device__ float  g_part[8ull * 16 * 128 * 128];  // gram partials: (B, 16 splits, C, C)
__device__ float  g_St[8ull * 128 * 128];         // sim transposed: [b][c][k]

struct alignas(16) H8 { __half2 a, b, c, d; };

// ---------------- kernel 1: dwconv s2 + BN + PReLU, fp32 -> fp16 p1, also emits x16 ----
__device__ __forceinline__ void load_row9(float* f, const float* rowp, int tx)
{
    float4 A = (tx > 0) ? *(const float4*)(rowp + tx * 8 - 4)
                        : make_float4(0.f, 0.f, 0.f, 0.f);
    float4 B = *(const float4*)(rowp + tx * 8);
    float4 C = *(const float4*)(rowp + tx * 8 + 4);
    f[0] = A.w;
    f[1] = B.x; f[2] = B.y; f[3] = B.z; f[4] = B.w;
    f[5] = C.x; f[6] = C.y; f[7] = C.z; f[8] = C.w;
}

__global__ void dwconv1_kernel(
    const float* __restrict__ in, __half* __restrict__ out, __half* __restrict__ x16,
    const float* __restrict__ w,
    const float* __restrict__ gamma, const float* __restrict__ beta,
    const float* __restrict__ mean, const float* __restrict__ var,
    const float* __restrict__ alpha)
{
    const int Win = 256, Wout = 128;
    int bc = blockIdx.z;               // b*128 + c
    int c  = bc & 127;
    int tx = threadIdx.x;              // 32 threads x 4 outputs
    int oy = blockIdx.x * blockDim.y + threadIdx.y;

    const float* ip = in + (size_t)bc * 65536;

    float w0 = w[c*9+0], w1 = w[c*9+1], w2 = w[c*9+2];
    float w3 = w[c*9+3], w4 = w[c*9+4], w5 = w[c*9+5];
    float w6 = w[c*9+6], w7 = w[c*9+7], w8 = w[c*9+8];
    float inv  = gamma[c] * rsqrtf(var[c] + EPSV);
    float bias = beta[c] - mean[c] * inv;
    float a    = alpha[c];

    int iy = 2 * oy;
    float f0[9], f1[9], f2[9];
    if (oy > 0) load_row9(f0, ip + (size_t)(iy - 1) * Win, tx);
    else {
#pragma unroll
        for (int i = 0; i < 9; ++i) f0[i] = 0.f;
    }
    load_row9(f1, ip + (size_t)iy * Win, tx);
    load_row9(f2, ip + (size_t)(iy + 1) * Win, tx);

    // ---- emit x16 for rows iy (from f1) and iy+1 (from f2), cols 8tx..8tx+7
    {
        __half* xo = x16 + (size_t)bc * 65536 + (size_t)iy * 256 + tx * 8;
        H8 r;
        r.a = __floats2half2_rn(f1[1], f1[2]);
        r.b = __floats2half2_rn(f1[3], f1[4]);
        r.c = __floats2half2_rn(f1[5], f1[6]);
        r.d = __floats2half2_rn(f1[7], f1[8]);
        *(H8*)xo = r;
        r.a = __floats2half2_rn(f2[1], f2[2]);
        r.b = __floats2half2_rn(f2[3], f2[4]);
        r.c = __floats2half2_rn(f2[5], f2[6]);
        r.d = __floats2half2_rn(f2[7], f2[8]);
        *(H8*)(xo + 256) = r;
    }

    float res[4];
#pragma unroll
    for (int j = 0; j < 4; ++j) {
        float s = w0 * f0[2*j] + w1 * f0[2*j+1] + w2 * f0[2*j+2]
                + w3 * f1[2*j] + w4 * f1[2*j+1] + w5 * f1[2*j+2]
                + w6 * f2[2*j] + w7 * f2[2*j+1] + w8 * f2[2*j+2];
        float y = s * inv + bias;
        res[j] = (y > 0.f) ? y : a * y;
    }
    __half2 h0 = __floats2half2_rn(res[0], res[1]);
    __half2 h1 = __floats2half2_rn(res[2], res[3]);
    __half* op = out + (size_t)bc * 16384 + (size_t)oy * Wout + tx * 4;
    *(__half2*)op       = h0;
    *(__half2*)(op + 2) = h1;
}

// ---------------- kernel 2: dwconv s2 + BN + PReLU, fp16 in -> fp16 out ----------------
__device__ __forceinline__ void load_row9h(float* f, const __half* rowp, int tx)
{
    if (tx > 0) {
        __half2 pv = *(const __half2*)(rowp + tx * 8 - 2);
        f[0] = __half2float(__high2half(pv));
    } else f[0] = 0.f;
    uint4 B = *(const uint4*)(rowp + tx * 8);
    const __half2* hb = (const __half2*)&B;
#pragma unroll
    for (int i = 0; i < 4; ++i) {
        float2 v = __half22float2(hb[i]);
        f[1 + 2*i] = v.x;
        f[2 + 2*i] = v.y;
    }
}

__global__ void dwconv2_kernel(
    const __half* __restrict__ in, __half* __restrict__ out,
    const float* __restrict__ w,
    const float* __restrict__ gamma, const float* __restrict__ beta,
    const float* __restrict__ mean, const float* __restrict__ var,
    const float* __restrict__ alpha)
{
    const int Win = 128, Wout = 64;
    int bc = blockIdx.z;
    int c  = bc & 127;
    int tx = threadIdx.x;              // 16 threads x 4 outputs
    int oy = blockIdx.x * blockDim.y + threadIdx.y;

    const __half* ip = in + (size_t)bc * 16384;

    float w0 = w[c*9+0], w1 = w[c*9+1], w2 = w[c*9+2];
    float w3 = w[c*9+3], w4 = w[c*9+4], w5 = w[c*9+5];
    float w6 = w[c*9+6], w7 = w[c*9+7], w8 = w[c*9+8];
    float inv  = gamma[c] * rsqrtf(var[c] + EPSV);
    float bias = beta[c] - mean[c] * inv;
    float a    = alpha[c];

    int iy = 2 * oy;
    float f0[9], f1[9], f2[9];
    if (oy > 0) load_row9h(f0, ip + (size_t)(iy - 1) * Win, tx);
    else {
#pragma unroll
        for (int i = 0; i < 9; ++i) f0[i] = 0.f;
    }
    load_row9h(f1, ip + (size_t)iy * Win, tx);
    load_row9h(f2, ip + (size_t)(iy + 1) * Win, tx);

    float res[4];
#pragma unroll
    for (int j = 0; j < 4; ++j) {
        float s = w0 * f0[2*j] + w1 * f0[2*j+1] + w2 * f0[2*j+2]
                + w3 * f1[2*j] + w4 * f1[2*j+1] + w5 * f1[2*j+2]
                + w6 * f2[2*j] + w7 * f2[2*j+1] + w8 * f2[2*j+2];
        float y = s * inv + bias;
        res[j] = (y > 0.f) ? y : a * y;
    }
    __half2 h0 = __floats2half2_rn(res[0], res[1]);
    __half2 h1 = __floats2half2_rn(res[2], res[3]);
    __half* op = out + (size_t)bc * 4096 + (size_t)oy * Wout + tx * 4;
    *(__half2*)op       = h0;
    *(__half2*)(op + 2) = h1;
}

// ---------------- common MMA helpers ----------------
__device__ __forceinline__ unsigned smem_u32(const void* p) {
    return (unsigned)__cvta_generic_to_shared(p);
}

#define LDSM_X4(r, addr) \
    asm volatile("ldmatrix.sync.aligned.m8n8.x4.shared.b16 {%0,%1,%2,%3},[%4];" \
        : "=r"((r)[0]), "=r"((r)[1]), "=r"((r)[2]), "=r"((r)[3]) : "r"(addr))

#define LDSM_X4_T(r, addr) \
    asm volatile("ldmatrix.sync.aligned.m8n8.x4.trans.shared.b16 {%0,%1,%2,%3},[%4];" \
        : "=r"((r)[0]), "=r"((r)[1]), "=r"((r)[2]), "=r"((r)[3]) : "r"(addr))

#define MMAF16(C, A, b0, b1) \
    asm volatile("mma.sync.aligned.m16n8k16.row.col.f32.f16.f16.f32 " \
        "{%0,%1,%2,%3},{%4,%5,%6,%7},{%8,%9},{%0,%1,%2,%3};" \
        : "+f"((C)[0]), "+f"((C)[1]), "+f"((C)[2]), "+f"((C)[3]) \
        : "r"((A)[0]), "r"((A)[1]), "r"((A)[2]), "r"((A)[3]), "r"(b0), "r"(b1))

#define CP_ASYNC16(dst, src) \
    asm volatile("cp.async.cg.shared.global [%0],[%1],16;" :: "r"(dst), "l"(src))
#define CP_COMMIT() asm volatile("cp.async.commit_group;")
#define CP_WAIT(n)  asm volatile("cp.async.wait_group %0;" :: "n"(n) : "memory")

// ---------------- kernel 3: gram partials via fp16 MMA ----------------
#define LDP 264

__global__ __launch_bounds__(256) void gram_mma_kernel()
{
    extern __shared__ __half P[];       // [128 c][LDP]
    int s = blockIdx.x, b = blockIdx.y;
    int tid = threadIdx.x, warp = tid >> 5, lane = tid & 31;

    const __half* src = g_p2h + (size_t)b * 524288 + s * 256;
#pragma unroll
    for (int i = 0; i < 16; ++i) {
        int idx = i * 256 + tid;
        int c = idx >> 5, j = idx & 31;
        *(uint4*)(P + c * LDP + j * 8) = *(const uint4*)(src + (size_t)c * 4096 + j * 8);
    }
    __syncthreads();

    int i0 = (warp >> 1) * 32;
    int j0 = (warp & 1) * 64;
    int r  = lane & 15, q = lane >> 4;
    int br = (lane & 7) | ((lane >> 4) << 3);
    int bq = (lane >> 3) & 1;

    float acc[2][8][4];
#pragma unroll
    for (int mf = 0; mf < 2; ++mf)
#pragma unroll
        for (int nf = 0; nf < 8; ++nf)
#pragma unroll
            for (int e = 0; e < 4; ++e) acc[mf][nf][e] = 0.f;

#pragma unroll
    for (int ks = 0; ks < 16; ++ks) {
        int k0 = ks * 16;
        unsigned ah[2][4];
#pragma unroll
        for (int mf = 0; mf < 2; ++mf)
            LDSM_X4(ah[mf], smem_u32(P + (i0 + mf * 16 + r) * LDP + k0 + q * 8));
#pragma unroll
        for (int nc = 0; nc < 4; ++nc) {
            unsigned bf[4];
            LDSM_X4(bf, smem_u32(P + (j0 + nc * 16 + br) * LDP + k0 + bq * 8));
#pragma unroll
            for (int mf = 0; mf < 2; ++mf) {
                MMAF16(acc[mf][nc * 2],     ah[mf], bf[0], bf[1]);
                MMAF16(acc[mf][nc * 2 + 1], ah[mf], bf[2], bf[3]);
            }
        }
    }

    float* dst = g_part + ((size_t)b * 16 + s) * 16384;
    int rbase = i0 + (lane >> 2);
    int cbase = j0 + ((lane & 3) << 1);
#pragma unroll
    for (int mf = 0; mf < 2; ++mf) {
#pragma unroll
        for (int nf = 0; nf < 8; ++nf) {
            float* p0 = dst + (size_t)(rbase + mf * 16) * 128 + cbase + nf * 8;
            float* p1 = p0 + 8 * 128;
            *(float2*)p0 = make_float2(acc[mf][nf][0], acc[mf][nf][1]);
            *(float2*)p1 = make_float2(acc[mf][nf][2], acc[mf][nf][3]);
        }
    }
}

// ---------------- kernel 4: reduce 16 partials, scale, softmax; TRANSPOSED store ----
__global__ void softmax_kernel()
{
    int i = blockIdx.x, b = blockIdx.y, j = threadIdx.x;
    const float* p = g_part + (size_t)b * 16 * 16384 + (size_t)i * 128 + j;
    float g = 0.f;
#pragma unroll
    for (int s = 0; s < 16; ++s) g += p[(size_t)s * 16384];
    g *= (1.0f / 64.0f);   // (64*64)^-0.5

    __shared__ float buf[128];
    buf[j] = g;
    __syncthreads();
    for (int off = 64; off > 0; off >>= 1) {
        if (j < off) buf[j] = fmaxf(buf[j], buf[j + off]);
        __syncthreads();
    }
    float m = buf[0];
    __syncthreads();
    float e = __expf(g - m);
    buf[j] = e;
    __syncthreads();
    for (int off = 64; off > 0; off >>= 1) {
        if (j < off) buf[j] = buf[j] + buf[j + off];
        __syncthreads();
    }
    float r = e / buf[0];
    g_St[(size_t)b * 16384 + (size_t)j * 128 + i] = r;   // [b][c][k]
}

// ---------------- kernel 5: attention einsum, fp16 MMA, B direct from x16 ----------------
#define LDA 136
#define LDB 72
#define TN  64
#define NSUB 8

// smem: A 128*136*2 + B double 2*128*72*2 = 34816 + 36864 = 71680  -> 3 CTAs/SM
#define ATTN_SMEM 71680

__global__ __launch_bounds__(256, 3) void attn_mma_kernel(const __half* __restrict__ x16,
                                                          float* __restrict__ out)
{
    extern __shared__ char smraw[];
    __half* Ahi = (__half*)smraw;              // [128 c][LDA k]
    __half* B0  = Ahi + 128 * LDA;             // [128 k][LDB n], double buffered
    __half* B1  = B0 + 128 * LDB;

    int b    = blockIdx.y;
    int tid  = threadIdx.x;
    int warp = tid >> 5, lane = tid & 31;

    const __half* xb = x16 + (size_t)b * 128 * 65536;
    float*        ob = out + (size_t)b * 128 * 65536;

    int n0base = blockIdx.x * (NSUB * TN);

    // ---- prefetch tile 0 into B0 (1024 16B chunks, 4/thread)
#pragma unroll
    for (int i = 0; i < 4; ++i) {
        int idx = i * 256 + tid;
        int k = idx >> 3, ch = idx & 7;
        CP_ASYNC16(smem_u32(B0 + k * LDB + ch * 8),
                   xb + (size_t)k * 65536 + n0base + ch * 8);
    }
    CP_COMMIT();

    // ---- A prep: g_St[b] ([c][k] fp32) -> fp16
    {
        const float* Sp = g_St + (size_t)b * 16384;
#pragma unroll
        for (int i = 0; i < 16; ++i) {
            int idx = i * 256 + tid;
            int c = idx >> 5, k4 = (idx & 31) * 4;
            float4 v = *(const float4*)(Sp + c * 128 + k4);
            __half* ph = Ahi + c * LDA + k4;
            *(__half2*)(ph)     = __floats2half2_rn(v.x, v.y);
            *(__half2*)(ph + 2) = __floats2half2_rn(v.z, v.w);
        }
    }

    int mw = (warp >> 1) * 32;
    int nw = (warp & 1) * 32;
    int r  = lane & 15, q = lane >> 4;

    for (int t = 0; t < NSUB; ++t) {
        __half* Bp = (t & 1) ? B1 : B0;
        __half* Bn = (t & 1) ? B0 : B1;
        int n0 = n0base + t * TN;

        // prefetch tile t+1 into the other buffer (safe: end-of-iter barrier of t-1)
        if (t + 1 < NSUB) {
            int n0n = n0 + TN;
#pragma unroll
            for (int i = 0; i < 4; ++i) {
                int idx = i * 256 + tid;
                int k = idx >> 3, ch = idx & 7;
                CP_ASYNC16(smem_u32(Bn + k * LDB + ch * 8),
                           xb + (size_t)k * 65536 + n0n + ch * 8);
            }
            CP_COMMIT();
            CP_WAIT(1);      // tile t complete; t+1 may remain in flight
        } else {
            CP_WAIT(0);
        }
        __syncthreads();     // B[t] visible to all (A too on first iter)

        float acc[2][4][4];
#pragma unroll
        for (int mf = 0; mf < 2; ++mf)
#pragma unroll
            for (int nf = 0; nf < 4; ++nf)
#pragma unroll
                for (int e = 0; e < 4; ++e) acc[mf][nf][e] = 0.f;

#pragma unroll
        for (int ks = 0; ks < 8; ++ks) {
            int k0 = ks * 16;
            unsigned ah[2][4];
#pragma unroll
            for (int mf = 0; mf < 2; ++mf)
                LDSM_X4(ah[mf], smem_u32(Ahi + (mw + mf * 16 + r) * LDA + k0 + q * 8));
#pragma unroll
            for (int nc = 0; nc < 2; ++nc) {
                unsigned bf[4];
                LDSM_X4_T(bf, smem_u32(Bp + (k0 + r) * LDB + nw + nc * 16 + q * 8));
#pragma unroll
                for (int mf = 0; mf < 2; ++mf) {
#pragma unroll
                    for (int h = 0; h < 2; ++h) {
                        float* C = acc[mf][nc * 2 + h];
                        MMAF16(C, ah[mf], bf[2 * h], bf[2 * h + 1]);
                    }
                }
            }
        }

        int rbase = mw + (lane >> 2);
        int cbase = nw + ((lane & 3) << 1);
#pragma unroll
        for (int mf = 0; mf < 2; ++mf) {
#pragma unroll
            for (int nf = 0; nf < 4; ++nf) {
                float* p0 = ob + (size_t)(rbase + mf * 16) * 65536 + n0 + cbase + nf * 8;
                float* p1 = p0 + 8ull * 65536;
                *(float2*)p0 = make_float2(acc[mf][nf][0], acc[mf][nf][1]);
                *(float2*)p1 = make_float2(acc[mf][nf][2], acc[mf][nf][3]);
            }
        }

        __syncthreads();     // all warps done reading B[t] before t+2 prefetch reuses it
    }
}

// ---------------- launch: single-stream sequence (R10 style) ----------------
extern "C" void kernel_launch(void* const* d_in, const int* in_sizes, int n_in,
                              void* d_out, int out_size)
{
    (void)in_sizes; (void)n_in; (void)out_size;
    const float* x    = (const float*)d_in[0];
    const float* c1w  = (const float*)d_in[1];
    const float* g1   = (const float*)d_in[2];
    const float* b1   = (const float*)d_in[3];
    const float* m1   = (const float*)d_in[4];
    const float* v1   = (const float*)d_in[5];
    const float* a1   = (const float*)d_in[6];
    const float* c2w  = (const float*)d_in[7];
    const float* g2   = (const float*)d_in[8];
    const float* b2   = (const float*)d_in[9];
    const float* m2   = (const float*)d_in[10];
    const float* v2   = (const float*)d_in[11];
    const float* a2   = (const float*)d_in[12];
    float* out = (float*)d_out;

    void* tmp;
    cudaGetSymbolAddress(&tmp, g_x16);  __half* x16 = (__half*)tmp;
    cudaGetSymbolAddress(&tmp, g_p1h);  __half* p1  = (__half*)tmp;
    cudaGetSymbolAddress(&tmp, g_p2h);  __half* p2  = (__half*)tmp;

    cudaFuncSetAttribute(gram_mma_kernel,
                         cudaFuncAttributeMaxDynamicSharedMemorySize, 128 * LDP * 2);
    cudaFuncSetAttribute(attn_mma_kernel,
                         cudaFuncAttributeMaxDynamicSharedMemorySize, ATTN_SMEM);

    dwconv1_kernel<<<dim3(16, 1, 1024), dim3(32, 8)>>>(
        x, p1, x16, c1w, g1, b1, m1, v1, a1);
    dwconv2_kernel<<<dim3(4, 1, 1024), dim3(16, 16)>>>(
        p1, p2, c2w, g2, b2, m2, v2, a2);
    gram_mma_kernel<<<dim3(16, 8), 256, 128 * LDP * 2>>>();
    softmax_kernel<<<dim3(128, 8), 128>>>();
    attn_mma_kernel<<<dim3(128, 8), 256, ATTN_SMEM>>>(x16, out);
}